// round 2
// baseline (speedup 1.0000x reference)
#include <cuda_runtime.h>

#define H     128
#define IN_D  8
#define TT    512
#define OUTD  4
#define FCH   64
#define MB    32
#define NTHR  256

typedef unsigned long long u64;

// transposed weights + folded constants
__device__ float g_WT0ih[IN_D * 512];
__device__ float g_WT0hh[H * 512];
__device__ float g_WT1ih[H * 512];
__device__ float g_WT1hh[H * 512];
__device__ float g_W1T[H * FCH];
__device__ float g_b0[512];
__device__ float g_b1[512];
__device__ float g_bnsc[H];
__device__ float g_bnsh[H];

__global__ void prep_kernel(const float* __restrict__ Wih0, const float* __restrict__ Whh0,
                            const float* __restrict__ bih0, const float* __restrict__ bhh0,
                            const float* __restrict__ Wih1, const float* __restrict__ Whh1,
                            const float* __restrict__ bih1, const float* __restrict__ bhh1,
                            const float* __restrict__ gam,  const float* __restrict__ bet,
                            const float* __restrict__ mean, const float* __restrict__ var,
                            const float* __restrict__ W1)
{
    int i = blockIdx.x * blockDim.x + threadIdx.x;
    int st = gridDim.x * blockDim.x;
    for (int idx = i; idx < IN_D * 512; idx += st) {
        int k = idx / 512, j = idx % 512;
        g_WT0ih[idx] = Wih0[j * IN_D + k];
    }
    for (int idx = i; idx < H * 512; idx += st) {
        int k = idx / 512, j = idx % 512;
        g_WT0hh[idx] = Whh0[j * H + k];
        g_WT1ih[idx] = Wih1[j * H + k];
        g_WT1hh[idx] = Whh1[j * H + k];
    }
    for (int idx = i; idx < 512; idx += st) {
        g_b0[idx] = bih0[idx] + bhh0[idx];
        g_b1[idx] = bih1[idx] + bhh1[idx];
    }
    for (int idx = i; idx < H * FCH; idx += st) {
        int k = idx / FCH, j = idx % FCH;
        g_W1T[idx] = W1[j * H + k];
    }
    for (int idx = i; idx < H; idx += st) {
        float s = gam[idx] * rsqrtf(var[idx] + 1e-5f);
        g_bnsc[idx] = s;
        g_bnsh[idx] = bet[idx] - mean[idx] * s;
    }
}

__device__ __forceinline__ u64 splat2(float x) {
    u64 r; unsigned xi = __float_as_uint(x);
    asm("mov.b64 %0, {%1, %1};" : "=l"(r) : "r"(xi));
    return r;
}
__device__ __forceinline__ void fma2(u64& d, u64 a, u64 b) {
    asm("fma.rn.f32x2 %0, %1, %2, %0;" : "+l"(d) : "l"(a), "l"(b));
}
__device__ __forceinline__ float2 unpk(u64 v) {
    unsigned lo, hi;
    asm("mov.b64 {%0, %1}, %2;" : "=r"(lo), "=r"(hi) : "l"(v));
    return make_float2(__uint_as_float(lo), __uint_as_float(hi));
}
__device__ __forceinline__ float sigm(float v)  { return __fdividef(1.f, 1.f + __expf(-v)); }
__device__ __forceinline__ float tanhh(float v) { return 2.f * __fdividef(1.f, 1.f + __expf(-2.f * v)) - 1.f; }

// acc[g][jj][mp] += a[k][m-pair] * W[k][g*128 + j0+jj]
__device__ __forceinline__ void accum(u64 (&acc)[4][2][4],
                                      const float* __restrict__ WT,
                                      const float* __restrict__ aT,
                                      int K, int m0, int j0)
{
    const float* wp = WT + j0;
    const float* ap = aT + m0;
#pragma unroll 4
    for (int k = 0; k < K; k++) {
        ulonglong2 v0 = *reinterpret_cast<const ulonglong2*>(ap);
        ulonglong2 v1 = *reinterpret_cast<const ulonglong2*>(ap + 4);
#pragma unroll
        for (int g = 0; g < 4; g++) {
            float2 w = *reinterpret_cast<const float2*>(wp + g * H);
            u64 w0 = splat2(w.x), w1 = splat2(w.y);
            fma2(acc[g][0][0], v0.x, w0); fma2(acc[g][0][1], v0.y, w0);
            fma2(acc[g][0][2], v1.x, w0); fma2(acc[g][0][3], v1.y, w0);
            fma2(acc[g][1][0], v0.x, w1); fma2(acc[g][1][1], v0.y, w1);
            fma2(acc[g][1][2], v1.x, w1); fma2(acc[g][1][3], v1.y, w1);
        }
        wp += 512; ap += MB;
    }
}

__device__ __forceinline__ void acc_init(u64 (&acc)[4][2][4], const float bg[4][2]) {
#pragma unroll
    for (int g = 0; g < 4; g++)
#pragma unroll
        for (int jj = 0; jj < 2; jj++) {
            u64 v = splat2(bg[g][jj]);
#pragma unroll
            for (int mp = 0; mp < 4; mp++) acc[g][jj][mp] = v;
        }
}

__device__ __forceinline__ void cell_epi(u64 (&acc)[4][2][4], float (&cst)[16],
                                         float* shHT, int m0, int j0,
                                         float* shHN, const float* shBN, bool dec)
{
#pragma unroll
    for (int jj = 0; jj < 2; jj++) {
        int j = j0 + jj;
        float bs = dec ? shBN[j] : 0.f;
        float bh = dec ? shBN[H + j] : 0.f;
#pragma unroll
        for (int mp = 0; mp < 4; mp++) {
            float2 zi = unpk(acc[0][jj][mp]);
            float2 zf = unpk(acc[1][jj][mp]);
            float2 zg = unpk(acc[2][jj][mp]);
            float2 zo = unpk(acc[3][jj][mp]);
            int ci = jj * 8 + mp * 2;
            int m  = m0 + mp * 2;
#pragma unroll
            for (int l = 0; l < 2; l++) {
                float zii = l ? zi.y : zi.x, zff = l ? zf.y : zf.x;
                float zgg = l ? zg.y : zg.x, zoo = l ? zo.y : zo.x;
                float c = sigm(zff) * cst[ci + l] + sigm(zii) * tanhh(zgg);
                cst[ci + l] = c;
                float h = sigm(zoo) * tanhh(c);
                shHT[j * MB + m + l] = h;
                if (dec && shHN) shHN[j * MB + m + l] = h * bs + bh;
            }
        }
    }
}

// smem layout (floats)
#define SM_X   0
#define SM_H0  (SM_X  + IN_D * MB)
#define SM_H1  (SM_H0 + H * MB)
#define SM_HN  (SM_H1 + H * MB)
#define SM_W1  (SM_HN + H * MB)
#define SM_O1  (SM_W1 + H * FCH)
#define SM_O2  (SM_O1 + MB * FCH)
#define SM_BN  (SM_O2 + MB * OUTD)
#define SM_TOT (SM_BN + 2 * H)

__global__ void __launch_bounds__(NTHR, 1)
lstm_main(const float* __restrict__ x,
          const float* __restrict__ W2, const float* __restrict__ b2,
          const float* __restrict__ Wf, const float* __restrict__ bf,
          const float* __restrict__ b1fc,
          float* __restrict__ out, int steps)
{
    extern __shared__ float sm[];
    float* shX  = sm + SM_X;
    float* shH0 = sm + SM_H0;
    float* shH1 = sm + SM_H1;
    float* shHN = sm + SM_HN;
    float* shW1 = sm + SM_W1;
    float* shO1 = sm + SM_O1;
    float* shO2 = sm + SM_O2;
    float* shBN = sm + SM_BN;

    const int tid = threadIdx.x;
    const int m0  = (tid >> 6) * 8;
    const int j0  = (tid & 63) * 2;
    const int b0  = blockIdx.x * MB;

    for (int i = tid; i < H * MB; i += NTHR) { shH0[i] = 0.f; shH1[i] = 0.f; }
    for (int i = tid; i < H * FCH; i += NTHR) shW1[i] = g_W1T[i];
    if (tid < H) { shBN[tid] = g_bnsc[tid]; shBN[H + tid] = g_bnsh[tid]; }

    float c0r[16], c1r[16];
#pragma unroll
    for (int i = 0; i < 16; i++) { c0r[i] = 0.f; c1r[i] = 0.f; }

    float b0g[4][2], b1g[4][2];
#pragma unroll
    for (int g = 0; g < 4; g++)
#pragma unroll
        for (int jj = 0; jj < 2; jj++) {
            b0g[g][jj] = g_b0[g * H + j0 + jj];
            b1g[g][jj] = g_b1[g * H + j0 + jj];
        }
    __syncthreads();

    const int total = TT + steps;
    for (int t = 0; t < total; t++) {
        if (t < TT) {
            int m = tid >> 3, ii = tid & 7;
            shX[ii * MB + m] = x[((size_t)(b0 + m) * TT + t) * IN_D + ii];
        }
        __syncthreads();

        u64 acc[4][2][4];
        // layer 0
        acc_init(acc, b0g);
        accum(acc, g_WT0ih, shX,  IN_D, m0, j0);
        accum(acc, g_WT0hh, shH0, H,    m0, j0);
        __syncthreads();
        cell_epi(acc, c0r, shH0, m0, j0, nullptr, nullptr, false);
        __syncthreads();

        // layer 1
        bool dec = (t >= TT);
        acc_init(acc, b1g);
        accum(acc, g_WT1ih, shH0, H, m0, j0);
        accum(acc, g_WT1hh, shH1, H, m0, j0);
        __syncthreads();
        cell_epi(acc, c1r, shH1, m0, j0, shHN, shBN, dec);
        __syncthreads();

        if (dec) {
            int d = t - TT;
            // FC1: relu(BN(h1) @ W1^T + b1)
            for (int idx = tid; idx < MB * FCH; idx += NTHR) {
                int m = idx >> 6, n = idx & 63;
                float s = b1fc[n];
#pragma unroll 8
                for (int k = 0; k < H; k++) s += shHN[k * MB + m] * shW1[k * FCH + n];
                shO1[idx] = fmaxf(s, 0.f);
            }
            __syncthreads();
            // FC2 + output
            if (tid < MB * OUTD) {
                int m = tid >> 2, o = tid & 3;
                float s = b2[o];
#pragma unroll 8
                for (int k = 0; k < FCH; k++) s += shO1[m * FCH + k] * W2[o * FCH + k];
                shO2[tid] = s;
                out[((size_t)(b0 + m) * steps + d) * OUTD + o] = s;
            }
            __syncthreads();
            // feedback: xin = out @ Wf^T + bf  -> shX (transposed)
            {
                int m = tid >> 3, i = tid & 7;
                float s = bf[i];
#pragma unroll
                for (int o = 0; o < OUTD; o++) s += shO2[m * OUTD + o] * Wf[i * OUTD + o];
                shX[i * MB + m] = s;
            }
            // next-iter top sync orders this write before reads
        }
    }
}

extern "C" void kernel_launch(void* const* d_in, const int* in_sizes, int n_in,
                              void* d_out, int out_size) {
    const float* x    = (const float*)d_in[0];
    const float* Wih0 = (const float*)d_in[1];
    const float* Whh0 = (const float*)d_in[2];
    const float* bih0 = (const float*)d_in[3];
    const float* bhh0 = (const float*)d_in[4];
    const float* Wih1 = (const float*)d_in[5];
    const float* Whh1 = (const float*)d_in[6];
    const float* bih1 = (const float*)d_in[7];
    const float* bhh1 = (const float*)d_in[8];
    const float* gam  = (const float*)d_in[9];
    const float* bet  = (const float*)d_in[10];
    const float* mean = (const float*)d_in[11];
    const float* var  = (const float*)d_in[12];
    const float* W1   = (const float*)d_in[13];
    const float* b1   = (const float*)d_in[14];
    const float* W2   = (const float*)d_in[15];
    const float* b2   = (const float*)d_in[16];
    const float* Wf   = (const float*)d_in[17];
    const float* bf   = (const float*)d_in[18];
    float* out = (float*)d_out;

    int B = in_sizes[0] / (TT * IN_D);
    int steps = out_size / (B * OUTD);

    static bool attr_done = false;
    if (!attr_done) {
        cudaFuncSetAttribute(lstm_main, cudaFuncAttributeMaxDynamicSharedMemorySize,
                             SM_TOT * sizeof(float));
        attr_done = true;
    }

    prep_kernel<<<256, 256>>>(Wih0, Whh0, bih0, bhh0, Wih1, Whh1, bih1, bhh1,
                              gam, bet, mean, var, W1);
    lstm_main<<<B / MB, NTHR, SM_TOT * sizeof(float)>>>(x, W2, b2, Wf, bf, b1, out, steps);
}